// round 7
// baseline (speedup 1.0000x reference)
#include <cuda_runtime.h>
#include <cuda_bf16.h>
#include <math.h>

#define NIMG 16
#define KTOP 5000
#define NSLOT 5120          // padded to 512*10
#define NMS_THREADS 512
#define NMS_ELEMS 10
#define BND_CAP 32768
#define TIE_CAP 512
#define NSORT 8192

// libdevice precise exp (immune to -use_fast_math substitution)
extern "C" __device__ float __nv_expf(float);

// ---------------- device scratch (static, no runtime allocation) ----------------
__device__ int   g_hist[NIMG][4096];
__device__ int   g_bucket[NIMG];
__device__ int   g_cntAbove[NIMG];
__device__ int   g_selCnt[NIMG];
__device__ int   g_bndCnt[NIMG];
__device__ unsigned long long g_sel[NIMG][KTOP];
__device__ unsigned long long g_bnd[NIMG][BND_CAP];

__device__ float g_x1[NIMG][NSLOT];
__device__ float g_y1[NIMG][NSLOT];
__device__ float g_x2[NIMG][NSLOT];
__device__ float g_y2[NIMG][NSLOT];
__device__ float g_sc[NIMG][NSLOT];
__device__ float g_cl[NIMG][NSLOT];

// order-preserving float -> uint key (ascending)
__device__ __forceinline__ unsigned f2k(float f) {
    unsigned u = __float_as_uint(f);
    return (u & 0x80000000u) ? ~u : (u | 0x80000000u);
}
__device__ __forceinline__ float k2f(unsigned k) {
    return (k & 0x80000000u) ? __uint_as_float(k & 0x7FFFFFFFu) : __uint_as_float(~k);
}
__device__ __forceinline__ unsigned long long umax64(unsigned long long a, unsigned long long b) {
    return a > b ? a : b;
}
// sigmoid exactly as XLA LogisticExpander: 1 / (1 + exp(-x)), IEEE rn ops
__device__ __forceinline__ float sigmoid_rn(float v) {
    return __fdiv_rn(1.0f, __fadd_rn(1.0f, __nv_expf(-v)));
}

// ---------------- K0: zero counters & hist ----------------
__global__ void k_zero() {
    int i = blockIdx.x * blockDim.x + threadIdx.x;
    int tot = NIMG * 4096;
    int* h = (int*)g_hist;
    for (int j = i; j < tot; j += gridDim.x * blockDim.x) h[j] = 0;
    if (i < NIMG) { g_selCnt[i] = 0; g_bndCnt[i] = 0; }
}

// ---------------- K1: per-image 12-bit histogram over one level ----------------
__global__ void k_hist(const float* __restrict__ cls, int n4) {
    __shared__ int h[4096];
    int t = threadIdx.x;
    for (int j = t; j < 4096; j += blockDim.x) h[j] = 0;
    __syncthreads();
    int b = blockIdx.y;
    const float4* p = ((const float4*)cls) + (size_t)b * (size_t)n4;
    for (int i = blockIdx.x * blockDim.x + t; i < n4; i += gridDim.x * blockDim.x) {
        float4 v = p[i];
        atomicAdd(&h[f2k(v.x) >> 20], 1);
        atomicAdd(&h[f2k(v.y) >> 20], 1);
        atomicAdd(&h[f2k(v.z) >> 20], 1);
        atomicAdd(&h[f2k(v.w) >> 20], 1);
    }
    __syncthreads();
    for (int j = t; j < 4096; j += blockDim.x) {
        int c = h[j];
        if (c) atomicAdd(&g_hist[b][j], c);
    }
}

// ---------------- K2: find threshold bucket per image ----------------
__global__ void k_bucket() {
    int b = blockIdx.x, t = threadIdx.x;
    __shared__ int ps[256];
    int s = 0;
#pragma unroll
    for (int j = 0; j < 16; j++) s += g_hist[b][t * 16 + j];
    ps[t] = s;
    __syncthreads();
    if (t == 0) {
        int cum = 0, grp = -1;
        for (int g = 255; g >= 0; g--) {
            if (cum + ps[g] >= KTOP) { grp = g; break; }
            cum += ps[g];
        }
        int bucket = grp * 16; // fallback
        for (int j = 15; j >= 0; j--) {
            int bin = grp * 16 + j;
            int c = g_hist[b][bin];
            if (cum + c >= KTOP) { bucket = bin; break; }
            cum += c;
        }
        g_bucket[b] = bucket;
        g_cntAbove[b] = cum;
    }
}

// ---------------- K3: compact pass ----------------
__global__ void k_compact(const float* __restrict__ cls, int n4, int hwlog, int aoff) {
    int b = blockIdx.y;
    unsigned bucket = (unsigned)g_bucket[b];
    const float4* p = ((const float4*)cls) + (size_t)b * (size_t)n4;
    int hwmask = (1 << hwlog) - 1;
    for (int i = blockIdx.x * blockDim.x + threadIdx.x; i < n4; i += gridDim.x * blockDim.x) {
        float4 v = p[i];
        float vv[4] = { v.x, v.y, v.z, v.w };
#pragma unroll
        for (int j = 0; j < 4; j++) {
            unsigned kk = f2k(vv[j]);
            unsigned bin = kk >> 20;
            if (bin >= bucket) {
                int e = i * 4 + j;              // element within image: ch*HW + pix
                int ch = e >> hwlog;
                int pix = e & hwmask;
                int a = ch / 90;
                int c = ch - a * 90;
                int n = aoff + pix * 9 + a;
                unsigned fidx = (unsigned)(n * 90 + c);
                unsigned long long rec = ((unsigned long long)kk << 32) | fidx;
                if (bin > bucket) {
                    int pos = atomicAdd(&g_selCnt[b], 1);
                    if (pos < KTOP) g_sel[b][pos] = rec;
                } else {
                    int pos = atomicAdd(&g_bndCnt[b], 1);
                    if (pos < BND_CAP) g_bnd[b][pos] = rec;
                }
            }
        }
    }
}

// ---------------- K4: refine boundary bucket, exact tie-break (lowest index) ----------------
__global__ void k_refine() {
    int b = blockIdx.x, t = threadIdx.x; // 256 threads
    __shared__ int h2[4096];
    __shared__ int ps[256];
    __shared__ int s_f2, s_above2, s_cnt2, s_tcnt;
    __shared__ unsigned long long tl[TIE_CAP];

    int n = g_bndCnt[b]; if (n > BND_CAP) n = BND_CAP;
    int above = g_cntAbove[b];
    int need = KTOP - above;

    for (int i = t; i < 4096; i += 256) h2[i] = 0;
    __syncthreads();
    for (int i = t; i < n; i += 256) {
        unsigned long long rec = g_bnd[b][i];
        int bin = (int)((rec >> 40) & 0xFFFu);  // key bits [19:8]
        atomicAdd(&h2[bin], 1);
    }
    __syncthreads();
    {
        int s = 0;
#pragma unroll
        for (int j = 0; j < 16; j++) s += h2[t * 16 + j];
        ps[t] = s;
    }
    __syncthreads();
    if (t == 0) {
        int cum = 0, grp = -1;
        for (int g = 255; g >= 0; g--) {
            if (cum + ps[g] >= need) { grp = g; break; }
            cum += ps[g];
        }
        int f2 = grp * 16;
        for (int j = 15; j >= 0; j--) {
            int bin = grp * 16 + j;
            int c = h2[bin];
            if (cum + c >= need) { f2 = bin; break; }
            cum += c;
        }
        s_f2 = f2; s_above2 = cum; s_cnt2 = 0; s_tcnt = 0;
    }
    __syncthreads();
    int f2 = s_f2, above2 = s_above2;
    for (int i = t; i < n; i += 256) {
        unsigned long long rec = g_bnd[b][i];
        int bin = (int)((rec >> 40) & 0xFFFu);
        if (bin > f2) {
            int p = atomicAdd(&s_cnt2, 1);
            if (above + p < KTOP) g_sel[b][above + p] = rec;
        } else if (bin == f2) {
            int p = atomicAdd(&s_tcnt, 1);
            if (p < TIE_CAP) tl[p] = rec;
        }
    }
    __syncthreads();
    int m = s_tcnt; if (m > TIE_CAP) m = TIE_CAP;
    int need3 = need - above2;
    for (int i = t; i < m; i += 256) {
        unsigned long long ri = tl[i];
        unsigned ki = (unsigned)(ri >> 32);
        unsigned xi = (unsigned)ri;
        int rank = 0;
        for (int j = 0; j < m; j++) {
            unsigned long long rj = tl[j];
            unsigned kj = (unsigned)(rj >> 32);
            unsigned xj = (unsigned)rj;
            rank += (kj > ki) || (kj == ki && xj < xi);
        }
        if (rank < need3) {
            int pos = above + above2 + rank;
            if (pos < KTOP) g_sel[b][pos] = ri;
        }
    }
}

// ---------------- K4b: per-image bitonic sort into exact top_k rank order ----------------
__global__ void __launch_bounds__(512, 1) k_sort() {
    extern __shared__ unsigned long long sk[];
    int b = blockIdx.x, t = threadIdx.x;
    for (int i = t; i < NSORT; i += 512) {
        unsigned long long v = 0ull;
        if (i < KTOP) {
            unsigned long long rec = g_sel[b][i];
            v = (rec & 0xFFFFFFFF00000000ull) |
                (unsigned long long)(0xFFFFFFFFu - (unsigned)rec);
        }
        sk[i] = v;
    }
    __syncthreads();
    for (int k = 2; k <= NSORT; k <<= 1) {
        for (int j = k >> 1; j > 0; j >>= 1) {
            for (int i = t; i < NSORT; i += 512) {
                int l = i ^ j;
                if (l > i) {
                    unsigned long long a = sk[i], c = sk[l];
                    bool up = ((i & k) == 0);
                    if ((a > c) == up) { sk[i] = c; sk[l] = a; }
                }
            }
            __syncthreads();
        }
    }
    for (int r = t; r < KTOP; r += 512) {
        unsigned long long v = sk[NSORT - 1 - r];
        unsigned long long rec = (v & 0xFFFFFFFF00000000ull) |
                                 (unsigned long long)(0xFFFFFFFFu - (unsigned)v);
        g_sel[b][r] = rec;
    }
}

// ---------------- K5: decode — match XLA's FMA-contracted lowering ----------------
struct BoxPtrs { const float* p[5]; };

__global__ void k_decode(BoxPtrs bp, const float* __restrict__ anchors) {
    int b = blockIdx.y;
    int k = blockIdx.x * blockDim.x + threadIdx.x;
    if (k >= NSLOT) return;
    if (k >= KTOP) {
        g_x1[b][k] = 0.f; g_y1[b][k] = 0.f; g_x2[b][k] = 0.f; g_y2[b][k] = 0.f;
        g_sc[b][k] = -1.f; g_cl[b][k] = 0.f;
        return;
    }
    unsigned long long rec = g_sel[b][k];
    unsigned key = (unsigned)(rec >> 32);
    unsigned fidx = (unsigned)rec;
    float v = k2f(key);
    float score = sigmoid_rn(v);

    int n = (int)(fidx / 90u);
    int c = (int)(fidx - (unsigned)n * 90u);

    int L, aoff, HW;
    if      (n < 36864) { L = 0; aoff = 0;     HW = 4096; }
    else if (n < 46080) { L = 1; aoff = 36864; HW = 1024; }
    else if (n < 48384) { L = 2; aoff = 46080; HW = 256;  }
    else if (n < 48960) { L = 3; aoff = 48384; HW = 64;   }
    else                { L = 4; aoff = 48960; HW = 16;   }
    int r = n - aoff;
    int pix = r / 9;
    int a = r - pix * 9;

    const float* bpp = bp.p[L] + ((size_t)b * 36 + (size_t)a * 4) * (size_t)HW + pix;
    float ty = bpp[0];
    float tx = bpp[HW];
    float th = bpp[2 * HW];
    float tw = bpp[3 * HW];

    float4 an = *(const float4*)(anchors + 4 * (size_t)n); // y1,x1,y2,x2
    float ya = __fmul_rn(__fadd_rn(an.x, an.z), 0.5f);
    float xa = __fmul_rn(__fadd_rn(an.y, an.w), 0.5f);
    float ha = __fsub_rn(an.z, an.x);
    float wa = __fsub_rn(an.w, an.y);
    float w  = __fmul_rn(__nv_expf(tw), wa);
    float h  = __fmul_rn(__nv_expf(th), ha);
    float yc = __fmaf_rn(ty, ha, ya);
    float xc = __fmaf_rn(tx, wa, xa);
    float x1 = __fmaf_rn(w, -0.5f, xc);
    float y1 = __fmaf_rn(h, -0.5f, yc);
    float x2 = __fmaf_rn(w,  0.5f, xc);
    float y2 = __fmaf_rn(h,  0.5f, yc);

    g_x1[b][k] = x1; g_y1[b][k] = y1; g_x2[b][k] = x2; g_y2[b][k] = y2;
    g_sc[b][k] = score;
    g_cl[b][k] = (float)c;
}

// ---------------- K6: gaussian soft-NMS, one CTA per image ----------------
__global__ void __launch_bounds__(NMS_THREADS, 1) k_nms(float* __restrict__ out) {
    extern __shared__ float sm[];
    float* sx1 = sm;
    float* sy1 = sm + NSLOT;
    float* sx2 = sm + 2 * NSLOT;
    float* sy2 = sm + 3 * NSLOT;
    float* scl = sm + 4 * NSLOT;
    __shared__ unsigned long long red[16];

    int b = blockIdx.x, t = threadIdx.x;

    float S[NMS_ELEMS], X1[NMS_ELEMS], Y1[NMS_ELEMS], X2[NMS_ELEMS], Y2[NMS_ELEMS], AR[NMS_ELEMS];
    unsigned long long best = 0ull;
#pragma unroll
    for (int e = 0; e < NMS_ELEMS; e++) {
        int sl = e * NMS_THREADS + t;
        float x1 = g_x1[b][sl], y1 = g_y1[b][sl], x2 = g_x2[b][sl], y2 = g_y2[b][sl];
        float s = g_sc[b][sl], cl = g_cl[b][sl];
        sx1[sl] = x1; sy1[sl] = y1; sx2[sl] = x2; sy2[sl] = y2; scl[sl] = cl;
        X1[e] = x1; Y1[e] = y1; X2[e] = x2; Y2[e] = y2; S[e] = s;
        AR[e] = __fmul_rn(__fsub_rn(x2, x1), __fsub_rn(y2, y1));
        unsigned kb = (s > 0.f) ? __float_as_uint(s) : 0u;
        best = umax64(best, ((unsigned long long)kb << 32) | (unsigned)(~sl));
    }
    __syncthreads();

    for (int it = 0; it < 100; it++) {
        unsigned long long v = best;
#pragma unroll
        for (int o = 16; o; o >>= 1) v = umax64(v, __shfl_down_sync(0xffffffffu, v, o));
        if ((t & 31) == 0) red[t >> 5] = v;
        __syncthreads();
        if (t < 32) {
            unsigned long long w = (t < 16) ? red[t] : 0ull;
#pragma unroll
            for (int o = 8; o; o >>= 1) w = umax64(w, __shfl_down_sync(0xffffffffu, w, o));
            if (t == 0) red[0] = w;
        }
        __syncthreads();
        unsigned long long ball = red[0];
        int slot = (int)(~(unsigned)ball);          // exact slot recovery (BUG FIX: no mask)
        float ps = __uint_as_float((unsigned)(ball >> 32));
        float px1 = sx1[slot], py1 = sy1[slot], px2 = sx2[slot], py2 = sy2[slot];
        float pdx = __fsub_rn(px2, px1);
        float pdy = __fsub_rn(py2, py1);
        if (t == 0) {
            float* o = out + ((size_t)b * 100 + it) * 6;
            o[0] = px1; o[1] = py1; o[2] = px2; o[3] = py2; o[4] = ps; o[5] = scl[slot];
        }
        best = 0ull;
#pragma unroll
        for (int e = 0; e < NMS_ELEMS; e++) {
            int sl = e * NMS_THREADS + t;
            float s = S[e];
            if (sl == slot) {
                s = -1.0f;
            } else if (s > 0.f) {
                float ix1 = fmaxf(px1, X1[e]);
                float iy1 = fmaxf(py1, Y1[e]);
                float ix2 = fminf(px2, X2[e]);
                float iy2 = fminf(py2, Y2[e]);
                float cw = __fsub_rn(ix2, ix1);
                float ch = __fsub_rn(iy2, iy1);
                if (cw > 0.f && ch > 0.f) {
                    float inter = __fmul_rn(cw, ch);
                    float t1 = __fmaf_rn(pdx, pdy, AR[e]);
                    float t2 = __fmaf_rn(-cw, ch, t1);
                    float den = __fadd_rn(t2, 1e-8f);
                    float iou = __fdiv_rn(inter, den);
                    float m2 = __fmul_rn(iou, iou);
                    float decay = __nv_expf(__fmul_rn(m2, -2.0f));
                    s = __fmul_rn(s, decay);
                }
            }
            S[e] = s;
            unsigned kb = (s > 0.f) ? __float_as_uint(s) : 0u;
            best = umax64(best, ((unsigned long long)kb << 32) | (unsigned)(~sl));
        }
        __syncthreads();
    }
}

// ---------------- host ----------------
extern "C" void kernel_launch(void* const* d_in, const int* in_sizes, int n_in,
                              void* d_out, int out_size) {
    const float* cls[5] = { 0,0,0,0,0 };
    const float* box[5] = { 0,0,0,0,0 };
    const float* anchors = 0;
    for (int i = 0; i < n_in; i++) {
        const float* p = (const float*)d_in[i];
        switch (in_sizes[i]) {
            case 53084160: cls[0] = p; break;
            case 13271040: cls[1] = p; break;
            case 3317760:  cls[2] = p; break;
            case 829440:   cls[3] = p; break;
            case 207360:   cls[4] = p; break;
            case 2359296:  box[0] = p; break;
            case 589824:   box[1] = p; break;
            case 147456:   box[2] = p; break;
            case 36864:    box[3] = p; break;
            case 9216:     box[4] = p; break;
            case 196416:   anchors = p; break;
            default: break;
        }
    }
    static const int HW[5]    = { 4096, 1024, 256, 64, 16 };
    static const int HWLOG[5] = { 12, 10, 8, 6, 4 };
    static const int AOFF[5]  = { 0, 36864, 46080, 48384, 48960 };

    k_zero<<<64, 256>>>();

    for (int L = 0; L < 5; L++) {
        int n4 = 810 * HW[L] / 4;                    // float4 per image
        int gx = (n4 + 256 * 64 - 1) / (256 * 64);
        if (gx < 1) gx = 1;
        k_hist<<<dim3(gx, NIMG), 256>>>(cls[L], n4);
    }
    k_bucket<<<NIMG, 256>>>();
    for (int L = 0; L < 5; L++) {
        int n4 = 810 * HW[L] / 4;
        int gx = (n4 + 256 * 64 - 1) / (256 * 64);
        if (gx < 1) gx = 1;
        k_compact<<<dim3(gx, NIMG), 256>>>(cls[L], n4, HWLOG[L], AOFF[L]);
    }
    k_refine<<<NIMG, 256>>>();

    int sort_smem = NSORT * (int)sizeof(unsigned long long);
    cudaFuncSetAttribute(k_sort, cudaFuncAttributeMaxDynamicSharedMemorySize, sort_smem);
    k_sort<<<NIMG, 512, sort_smem>>>();

    BoxPtrs bp;
    for (int L = 0; L < 5; L++) bp.p[L] = box[L];
    k_decode<<<dim3(NSLOT / 256, NIMG), 256>>>(bp, anchors);

    int smem = 5 * NSLOT * (int)sizeof(float);
    cudaFuncSetAttribute(k_nms, cudaFuncAttributeMaxDynamicSharedMemorySize, smem);
    k_nms<<<NIMG, NMS_THREADS, smem>>>((float*)d_out);
}

// round 8
// speedup vs baseline: 1.0239x; 1.0239x over previous
#include <cuda_runtime.h>
#include <cuda_bf16.h>
#include <math.h>

#define NIMG 16
#define KTOP 5000
#define NSLOT 5120          // padded to 512*10
#define NMS_THREADS 512
#define NMS_ELEMS 10
#define BND_CAP 32768
#define TIE_CAP 512
#define NSORT 8192
#define SEL_BINS 16384

// libdevice precise exp (immune to -use_fast_math substitution)
extern "C" __device__ float __nv_expf(float);

// ---------------- device scratch (static, no runtime allocation) ----------------
__device__ int   g_hist[NIMG][4096];
__device__ int   g_bucket[NIMG];
__device__ int   g_cntAbove[NIMG];
__device__ int   g_selCnt[NIMG];
__device__ int   g_bndCnt[NIMG];
__device__ int   g_fb;                      // fallback flag
__device__ unsigned long long g_sel[NIMG][KTOP];
__device__ unsigned long long g_bnd[NIMG][BND_CAP];

__device__ float g_x1[NIMG][NSLOT];
__device__ float g_y1[NIMG][NSLOT];
__device__ float g_x2[NIMG][NSLOT];
__device__ float g_y2[NIMG][NSLOT];
__device__ float g_sc[NIMG][NSLOT];
__device__ float g_cl[NIMG][NSLOT];

struct Levels {
    const float* cls[5];
    int n4[5];      // float4 per image
    int hwlog[5];
    int aoff[5];
};

// order-preserving float -> uint key (ascending)
__device__ __forceinline__ unsigned f2k(float f) {
    unsigned u = __float_as_uint(f);
    return (u & 0x80000000u) ? ~u : (u | 0x80000000u);
}
__device__ __forceinline__ float k2f(unsigned k) {
    return (k & 0x80000000u) ? __uint_as_float(k & 0x7FFFFFFFu) : __uint_as_float(~k);
}
__device__ __forceinline__ unsigned long long umax64(unsigned long long a, unsigned long long b) {
    return a > b ? a : b;
}
__device__ __forceinline__ float sigmoid_rn(float v) {
    return __fdiv_rn(1.0f, __fadd_rn(1.0f, __nv_expf(-v)));
}
// monotone (non-decreasing) 14-bit bin over candidate keys; exact order within
// a bin is resolved by full-key tie ranking, so clamping stays correct.
__device__ __forceinline__ unsigned selbin(unsigned kk) {
    if (kk < 0xC0200000u) return 0u;
    unsigned d = (kk - 0xC0200000u) >> 14;
    return d > (SEL_BINS - 1) ? (SEL_BINS - 1) : d;
}

#define THRESH 2.6f

// ---------------- K0: zero counters & hist & flag ----------------
__global__ void k_zero() {
    int i = blockIdx.x * blockDim.x + threadIdx.x;
    int tot = NIMG * 4096;
    int* h = (int*)g_hist;
    for (int j = i; j < tot; j += gridDim.x * blockDim.x) h[j] = 0;
    if (i < NIMG) { g_selCnt[i] = 0; g_bndCnt[i] = 0; }
    if (i == 0) g_fb = 0;
}

// ---------------- K1: fused single sweep — compact everything >= THRESH ----------------
__global__ void k_sweep(Levels lv) {
    int L = blockIdx.z;
    int n4 = lv.n4[L];
    int b = blockIdx.y;
    const float4* p = ((const float4*)lv.cls[L]) + (size_t)b * (size_t)n4;
    int hwlog = lv.hwlog[L];
    int hwmask = (1 << hwlog) - 1;
    int aoff = lv.aoff[L];
    int stride = gridDim.x * blockDim.x;
    for (int i = blockIdx.x * blockDim.x + threadIdx.x; i < n4; i += stride) {
        float4 v = p[i];
        float mx = fmaxf(fmaxf(v.x, v.y), fmaxf(v.z, v.w));
        if (mx >= THRESH) {
            float vv[4] = { v.x, v.y, v.z, v.w };
#pragma unroll
            for (int j = 0; j < 4; j++) {
                if (vv[j] >= THRESH) {
                    int e = i * 4 + j;
                    int ch = e >> hwlog;
                    int pix = e & hwmask;
                    int a = ch / 90;
                    int c = ch - a * 90;
                    int n = aoff + pix * 9 + a;
                    unsigned fidx = (unsigned)(n * 90 + c);
                    unsigned long long rec = ((unsigned long long)f2k(vv[j]) << 32) | fidx;
                    int pos = atomicAdd(&g_bndCnt[b], 1);
                    if (pos < BND_CAP) g_bnd[b][pos] = rec;
                }
            }
        }
    }
}

// ---------------- K2: validate speculation ----------------
__global__ void k_check() {
    if (threadIdx.x == 0 && blockIdx.x == 0) {
        int fb = 0;
        for (int b = 0; b < NIMG; b++) {
            int c = g_bndCnt[b];
            if (c < KTOP || c > BND_CAP) fb = 1;
        }
        if (fb) g_fb = 1;
    }
}

// ---------------- K3: exact top-KTOP from candidates (speculative path) ----------------
__global__ void __launch_bounds__(256, 1) k_selectA() {
    if (g_fb) return;
    extern __shared__ int h[];                 // SEL_BINS ints
    __shared__ int ps[256];
    __shared__ int s_f, s_above, s_cnt, s_tcnt;
    __shared__ unsigned long long tl[TIE_CAP];

    int b = blockIdx.x, t = threadIdx.x;
    int n = g_bndCnt[b];                       // in [KTOP, BND_CAP] on this path

    for (int i = t; i < SEL_BINS; i += 256) h[i] = 0;
    __syncthreads();
    for (int i = t; i < n; i += 256) {
        unsigned kk = (unsigned)(g_bnd[b][i] >> 32);
        atomicAdd(&h[selbin(kk)], 1);
    }
    __syncthreads();
    {
        int s = 0;
#pragma unroll
        for (int j = 0; j < SEL_BINS / 256; j++) s += h[t * (SEL_BINS / 256) + j];
        ps[t] = s;
    }
    __syncthreads();
    if (t == 0) {
        int cum = 0, grp = 0;
        for (int g = 255; g >= 0; g--) {
            if (cum + ps[g] >= KTOP) { grp = g; break; }
            cum += ps[g];
        }
        int f = grp * (SEL_BINS / 256);
        for (int j = SEL_BINS / 256 - 1; j >= 0; j--) {
            int bin = grp * (SEL_BINS / 256) + j;
            int c = h[bin];
            if (cum + c >= KTOP) { f = bin; break; }
            cum += c;
        }
        s_f = f; s_above = cum; s_cnt = 0; s_tcnt = 0;
    }
    __syncthreads();
    int f = s_f;
    for (int i = t; i < n; i += 256) {
        unsigned long long rec = g_bnd[b][i];
        int bin = (int)selbin((unsigned)(rec >> 32));
        if (bin > f) {
            int p = atomicAdd(&s_cnt, 1);
            g_sel[b][p] = rec;
        } else if (bin == f) {
            int p = atomicAdd(&s_tcnt, 1);
            if (p < TIE_CAP) tl[p] = rec;
        }
    }
    __syncthreads();
    if (s_tcnt > TIE_CAP) {                    // pathological ties -> exact fallback
        if (t == 0) g_fb = 1;
        return;
    }
    int m = s_tcnt;
    int above = s_above;
    int need = KTOP - above;
    for (int i = t; i < m; i += 256) {
        unsigned long long ri = tl[i];
        unsigned ki = (unsigned)(ri >> 32);
        unsigned xi = (unsigned)ri;
        int rank = 0;
        for (int j = 0; j < m; j++) {
            unsigned long long rj = tl[j];
            unsigned kj = (unsigned)(rj >> 32);
            unsigned xj = (unsigned)rj;
            rank += (kj > ki) || (kj == ki && xj < xi);
        }
        if (rank < need) g_sel[b][above + rank] = ri;
    }
}

// ================= fallback path (flag-guarded, early-exit when speculation ok) =================

__global__ void k_fzero() {
    if (!g_fb) return;
    int i = threadIdx.x;
    if (i < NIMG) { g_bndCnt[i] = 0; g_selCnt[i] = 0; }
}

__global__ void k_histF(Levels lv) {
    if (!g_fb) return;
    __shared__ int h[4096];
    int t = threadIdx.x;
    for (int j = t; j < 4096; j += blockDim.x) h[j] = 0;
    __syncthreads();
    int L = blockIdx.z;
    int n4 = lv.n4[L];
    int b = blockIdx.y;
    const float4* p = ((const float4*)lv.cls[L]) + (size_t)b * (size_t)n4;
    for (int i = blockIdx.x * blockDim.x + t; i < n4; i += gridDim.x * blockDim.x) {
        float4 v = p[i];
        atomicAdd(&h[f2k(v.x) >> 20], 1);
        atomicAdd(&h[f2k(v.y) >> 20], 1);
        atomicAdd(&h[f2k(v.z) >> 20], 1);
        atomicAdd(&h[f2k(v.w) >> 20], 1);
    }
    __syncthreads();
    for (int j = t; j < 4096; j += blockDim.x) {
        int c = h[j];
        if (c) atomicAdd(&g_hist[b][j], c);
    }
}

__global__ void k_bucketF() {
    if (!g_fb) return;
    int b = blockIdx.x, t = threadIdx.x;
    __shared__ int ps[256];
    int s = 0;
#pragma unroll
    for (int j = 0; j < 16; j++) s += g_hist[b][t * 16 + j];
    ps[t] = s;
    __syncthreads();
    if (t == 0) {
        int cum = 0, grp = -1;
        for (int g = 255; g >= 0; g--) {
            if (cum + ps[g] >= KTOP) { grp = g; break; }
            cum += ps[g];
        }
        int bucket = grp * 16;
        for (int j = 15; j >= 0; j--) {
            int bin = grp * 16 + j;
            int c = g_hist[b][bin];
            if (cum + c >= KTOP) { bucket = bin; break; }
            cum += c;
        }
        g_bucket[b] = bucket;
        g_cntAbove[b] = cum;
    }
}

__global__ void k_compactF(Levels lv) {
    if (!g_fb) return;
    int L = blockIdx.z;
    int n4 = lv.n4[L];
    int b = blockIdx.y;
    unsigned bucket = (unsigned)g_bucket[b];
    const float4* p = ((const float4*)lv.cls[L]) + (size_t)b * (size_t)n4;
    int hwlog = lv.hwlog[L];
    int hwmask = (1 << hwlog) - 1;
    int aoff = lv.aoff[L];
    for (int i = blockIdx.x * blockDim.x + threadIdx.x; i < n4; i += gridDim.x * blockDim.x) {
        float4 v = p[i];
        float vv[4] = { v.x, v.y, v.z, v.w };
#pragma unroll
        for (int j = 0; j < 4; j++) {
            unsigned kk = f2k(vv[j]);
            unsigned bin = kk >> 20;
            if (bin >= bucket) {
                int e = i * 4 + j;
                int ch = e >> hwlog;
                int pix = e & hwmask;
                int a = ch / 90;
                int c = ch - a * 90;
                int n = aoff + pix * 9 + a;
                unsigned fidx = (unsigned)(n * 90 + c);
                unsigned long long rec = ((unsigned long long)kk << 32) | fidx;
                if (bin > bucket) {
                    int pos = atomicAdd(&g_selCnt[b], 1);
                    if (pos < KTOP) g_sel[b][pos] = rec;
                } else {
                    int pos = atomicAdd(&g_bndCnt[b], 1);
                    if (pos < BND_CAP) g_bnd[b][pos] = rec;
                }
            }
        }
    }
}

__global__ void k_refineF() {
    if (!g_fb) return;
    int b = blockIdx.x, t = threadIdx.x; // 256 threads
    __shared__ int h2[4096];
    __shared__ int ps[256];
    __shared__ int s_f2, s_above2, s_cnt2, s_tcnt;
    __shared__ unsigned long long tl[TIE_CAP];

    int n = g_bndCnt[b]; if (n > BND_CAP) n = BND_CAP;
    int above = g_cntAbove[b];
    int need = KTOP - above;

    for (int i = t; i < 4096; i += 256) h2[i] = 0;
    __syncthreads();
    for (int i = t; i < n; i += 256) {
        unsigned long long rec = g_bnd[b][i];
        int bin = (int)((rec >> 40) & 0xFFFu);
        atomicAdd(&h2[bin], 1);
    }
    __syncthreads();
    {
        int s = 0;
#pragma unroll
        for (int j = 0; j < 16; j++) s += h2[t * 16 + j];
        ps[t] = s;
    }
    __syncthreads();
    if (t == 0) {
        int cum = 0, grp = -1;
        for (int g = 255; g >= 0; g--) {
            if (cum + ps[g] >= need) { grp = g; break; }
            cum += ps[g];
        }
        int f2 = grp * 16;
        for (int j = 15; j >= 0; j--) {
            int bin = grp * 16 + j;
            int c = h2[bin];
            if (cum + c >= need) { f2 = bin; break; }
            cum += c;
        }
        s_f2 = f2; s_above2 = cum; s_cnt2 = 0; s_tcnt = 0;
    }
    __syncthreads();
    int f2 = s_f2, above2 = s_above2;
    for (int i = t; i < n; i += 256) {
        unsigned long long rec = g_bnd[b][i];
        int bin = (int)((rec >> 40) & 0xFFFu);
        if (bin > f2) {
            int p = atomicAdd(&s_cnt2, 1);
            if (above + p < KTOP) g_sel[b][above + p] = rec;
        } else if (bin == f2) {
            int p = atomicAdd(&s_tcnt, 1);
            if (p < TIE_CAP) tl[p] = rec;
        }
    }
    __syncthreads();
    int m = s_tcnt; if (m > TIE_CAP) m = TIE_CAP;
    int need3 = need - above2;
    for (int i = t; i < m; i += 256) {
        unsigned long long ri = tl[i];
        unsigned ki = (unsigned)(ri >> 32);
        unsigned xi = (unsigned)ri;
        int rank = 0;
        for (int j = 0; j < m; j++) {
            unsigned long long rj = tl[j];
            unsigned kj = (unsigned)(rj >> 32);
            unsigned xj = (unsigned)rj;
            rank += (kj > ki) || (kj == ki && xj < xi);
        }
        if (rank < need3) {
            int pos = above + above2 + rank;
            if (pos < KTOP) g_sel[b][pos] = ri;
        }
    }
}

// ---------------- K4b: per-image bitonic sort into exact top_k rank order ----------------
__global__ void __launch_bounds__(512, 1) k_sort() {
    extern __shared__ unsigned long long sk[];
    int b = blockIdx.x, t = threadIdx.x;
    for (int i = t; i < NSORT; i += 512) {
        unsigned long long v = 0ull;
        if (i < KTOP) {
            unsigned long long rec = g_sel[b][i];
            v = (rec & 0xFFFFFFFF00000000ull) |
                (unsigned long long)(0xFFFFFFFFu - (unsigned)rec);
        }
        sk[i] = v;
    }
    __syncthreads();
    for (int k = 2; k <= NSORT; k <<= 1) {
        for (int j = k >> 1; j > 0; j >>= 1) {
            for (int i = t; i < NSORT; i += 512) {
                int l = i ^ j;
                if (l > i) {
                    unsigned long long a = sk[i], c = sk[l];
                    bool up = ((i & k) == 0);
                    if ((a > c) == up) { sk[i] = c; sk[l] = a; }
                }
            }
            __syncthreads();
        }
    }
    for (int r = t; r < KTOP; r += 512) {
        unsigned long long v = sk[NSORT - 1 - r];
        unsigned long long rec = (v & 0xFFFFFFFF00000000ull) |
                                 (unsigned long long)(0xFFFFFFFFu - (unsigned)v);
        g_sel[b][r] = rec;
    }
}

// ---------------- K5: decode — match XLA's FMA-contracted lowering ----------------
struct BoxPtrs { const float* p[5]; };

__global__ void k_decode(BoxPtrs bp, const float* __restrict__ anchors) {
    int b = blockIdx.y;
    int k = blockIdx.x * blockDim.x + threadIdx.x;
    if (k >= NSLOT) return;
    if (k >= KTOP) {
        g_x1[b][k] = 0.f; g_y1[b][k] = 0.f; g_x2[b][k] = 0.f; g_y2[b][k] = 0.f;
        g_sc[b][k] = -1.f; g_cl[b][k] = 0.f;
        return;
    }
    unsigned long long rec = g_sel[b][k];
    unsigned key = (unsigned)(rec >> 32);
    unsigned fidx = (unsigned)rec;
    float v = k2f(key);
    float score = sigmoid_rn(v);

    int n = (int)(fidx / 90u);
    int c = (int)(fidx - (unsigned)n * 90u);

    int L, aoff, HW;
    if      (n < 36864) { L = 0; aoff = 0;     HW = 4096; }
    else if (n < 46080) { L = 1; aoff = 36864; HW = 1024; }
    else if (n < 48384) { L = 2; aoff = 46080; HW = 256;  }
    else if (n < 48960) { L = 3; aoff = 48384; HW = 64;   }
    else                { L = 4; aoff = 48960; HW = 16;   }
    int r = n - aoff;
    int pix = r / 9;
    int a = r - pix * 9;

    const float* bpp = bp.p[L] + ((size_t)b * 36 + (size_t)a * 4) * (size_t)HW + pix;
    float ty = bpp[0];
    float tx = bpp[HW];
    float th = bpp[2 * HW];
    float tw = bpp[3 * HW];

    float4 an = *(const float4*)(anchors + 4 * (size_t)n); // y1,x1,y2,x2
    float ya = __fmul_rn(__fadd_rn(an.x, an.z), 0.5f);
    float xa = __fmul_rn(__fadd_rn(an.y, an.w), 0.5f);
    float ha = __fsub_rn(an.z, an.x);
    float wa = __fsub_rn(an.w, an.y);
    float w  = __fmul_rn(__nv_expf(tw), wa);
    float h  = __fmul_rn(__nv_expf(th), ha);
    float yc = __fmaf_rn(ty, ha, ya);
    float xc = __fmaf_rn(tx, wa, xa);
    float x1 = __fmaf_rn(w, -0.5f, xc);
    float y1 = __fmaf_rn(h, -0.5f, yc);
    float x2 = __fmaf_rn(w,  0.5f, xc);
    float y2 = __fmaf_rn(h,  0.5f, yc);

    g_x1[b][k] = x1; g_y1[b][k] = y1; g_x2[b][k] = x2; g_y2[b][k] = y2;
    g_sc[b][k] = score;
    g_cl[b][k] = (float)c;
}

// ---------------- K6: gaussian soft-NMS, one CTA per image ----------------
__global__ void __launch_bounds__(NMS_THREADS, 1) k_nms(float* __restrict__ out) {
    extern __shared__ float sm[];
    float* sx1 = sm;
    float* sy1 = sm + NSLOT;
    float* sx2 = sm + 2 * NSLOT;
    float* sy2 = sm + 3 * NSLOT;
    float* scl = sm + 4 * NSLOT;
    __shared__ unsigned long long red[16];

    int b = blockIdx.x, t = threadIdx.x;

    float S[NMS_ELEMS], X1[NMS_ELEMS], Y1[NMS_ELEMS], X2[NMS_ELEMS], Y2[NMS_ELEMS], AR[NMS_ELEMS];
    unsigned long long best = 0ull;
#pragma unroll
    for (int e = 0; e < NMS_ELEMS; e++) {
        int sl = e * NMS_THREADS + t;
        float x1 = g_x1[b][sl], y1 = g_y1[b][sl], x2 = g_x2[b][sl], y2 = g_y2[b][sl];
        float s = g_sc[b][sl], cl = g_cl[b][sl];
        sx1[sl] = x1; sy1[sl] = y1; sx2[sl] = x2; sy2[sl] = y2; scl[sl] = cl;
        X1[e] = x1; Y1[e] = y1; X2[e] = x2; Y2[e] = y2; S[e] = s;
        AR[e] = __fmul_rn(__fsub_rn(x2, x1), __fsub_rn(y2, y1));
        unsigned kb = (s > 0.f) ? __float_as_uint(s) : 0u;
        best = umax64(best, ((unsigned long long)kb << 32) | (unsigned)(~sl));
    }
    __syncthreads();

    for (int it = 0; it < 100; it++) {
        unsigned long long v = best;
#pragma unroll
        for (int o = 16; o; o >>= 1) v = umax64(v, __shfl_down_sync(0xffffffffu, v, o));
        if ((t & 31) == 0) red[t >> 5] = v;
        __syncthreads();
        if (t < 32) {
            unsigned long long w = (t < 16) ? red[t] : 0ull;
#pragma unroll
            for (int o = 8; o; o >>= 1) w = umax64(w, __shfl_down_sync(0xffffffffu, w, o));
            if (t == 0) red[0] = w;
        }
        __syncthreads();
        unsigned long long ball = red[0];
        int slot = (int)(~(unsigned)ball);
        float ps = __uint_as_float((unsigned)(ball >> 32));
        float px1 = sx1[slot], py1 = sy1[slot], px2 = sx2[slot], py2 = sy2[slot];
        float pdx = __fsub_rn(px2, px1);
        float pdy = __fsub_rn(py2, py1);
        if (t == 0) {
            float* o = out + ((size_t)b * 100 + it) * 6;
            o[0] = px1; o[1] = py1; o[2] = px2; o[3] = py2; o[4] = ps; o[5] = scl[slot];
        }
        best = 0ull;
#pragma unroll
        for (int e = 0; e < NMS_ELEMS; e++) {
            int sl = e * NMS_THREADS + t;
            float s = S[e];
            if (sl == slot) {
                s = -1.0f;
            } else if (s > 0.f) {
                float ix1 = fmaxf(px1, X1[e]);
                float iy1 = fmaxf(py1, Y1[e]);
                float ix2 = fminf(px2, X2[e]);
                float iy2 = fminf(py2, Y2[e]);
                float cw = __fsub_rn(ix2, ix1);
                float ch = __fsub_rn(iy2, iy1);
                if (cw > 0.f && ch > 0.f) {
                    float inter = __fmul_rn(cw, ch);
                    float t1 = __fmaf_rn(pdx, pdy, AR[e]);
                    float t2 = __fmaf_rn(-cw, ch, t1);
                    float den = __fadd_rn(t2, 1e-8f);
                    float iou = __fdiv_rn(inter, den);
                    float m2 = __fmul_rn(iou, iou);
                    float decay = __nv_expf(__fmul_rn(m2, -2.0f));
                    s = __fmul_rn(s, decay);
                }
            }
            S[e] = s;
            unsigned kb = (s > 0.f) ? __float_as_uint(s) : 0u;
            best = umax64(best, ((unsigned long long)kb << 32) | (unsigned)(~sl));
        }
        __syncthreads();
    }
}

// ---------------- host ----------------
extern "C" void kernel_launch(void* const* d_in, const int* in_sizes, int n_in,
                              void* d_out, int out_size) {
    const float* cls[5] = { 0,0,0,0,0 };
    const float* box[5] = { 0,0,0,0,0 };
    const float* anchors = 0;
    for (int i = 0; i < n_in; i++) {
        const float* p = (const float*)d_in[i];
        switch (in_sizes[i]) {
            case 53084160: cls[0] = p; break;
            case 13271040: cls[1] = p; break;
            case 3317760:  cls[2] = p; break;
            case 829440:   cls[3] = p; break;
            case 207360:   cls[4] = p; break;
            case 2359296:  box[0] = p; break;
            case 589824:   box[1] = p; break;
            case 147456:   box[2] = p; break;
            case 36864:    box[3] = p; break;
            case 9216:     box[4] = p; break;
            case 196416:   anchors = p; break;
            default: break;
        }
    }
    static const int HW[5]    = { 4096, 1024, 256, 64, 16 };
    static const int HWLOG[5] = { 12, 10, 8, 6, 4 };
    static const int AOFF[5]  = { 0, 36864, 46080, 48384, 48960 };

    Levels lv;
    for (int L = 0; L < 5; L++) {
        lv.cls[L] = cls[L];
        lv.n4[L] = 810 * HW[L] / 4;
        lv.hwlog[L] = HWLOG[L];
        lv.aoff[L] = AOFF[L];
    }

    k_zero<<<64, 256>>>();

    // speculative single sweep over all levels
    k_sweep<<<dim3(256, NIMG, 5), 256>>>(lv);
    k_check<<<1, 1>>>();

    int sel_smem = SEL_BINS * (int)sizeof(int);
    cudaFuncSetAttribute(k_selectA, cudaFuncAttributeMaxDynamicSharedMemorySize, sel_smem);
    k_selectA<<<NIMG, 256, sel_smem>>>();

    // guarded exact fallback (early-exits when speculation validated)
    k_fzero<<<1, 32>>>();
    k_histF<<<dim3(64, NIMG, 5), 256>>>(lv);
    k_bucketF<<<NIMG, 256>>>();
    k_compactF<<<dim3(64, NIMG, 5), 256>>>(lv);
    k_refineF<<<NIMG, 256>>>();

    int sort_smem = NSORT * (int)sizeof(unsigned long long);
    cudaFuncSetAttribute(k_sort, cudaFuncAttributeMaxDynamicSharedMemorySize, sort_smem);
    k_sort<<<NIMG, 512, sort_smem>>>();

    BoxPtrs bp;
    for (int L = 0; L < 5; L++) bp.p[L] = box[L];
    k_decode<<<dim3(NSLOT / 256, NIMG), 256>>>(bp, anchors);

    int smem = 5 * NSLOT * (int)sizeof(float);
    cudaFuncSetAttribute(k_nms, cudaFuncAttributeMaxDynamicSharedMemorySize, smem);
    k_nms<<<NIMG, NMS_THREADS, smem>>>((float*)d_out);
}